// round 4
// baseline (speedup 1.0000x reference)
#include <cuda_runtime.h>
#include <cuda_bf16.h>
#include <math.h>

// Problem constants
#define NN        8192      // nodes
#define DIM       256       // in_dim == out_dim
#define SCALE     0.0625f   // 1/sqrt(256)
#define CHUNK_CAP 64        // per-1024-col chunk edge cap (mean ~10, P(>63) ~ 1e-30)

// ---------------- scratch (static device memory; no allocs allowed) --------
__device__ float g_Q[(size_t)NN * DIM];                 // SCALE * Q, fp32
__device__ float g_V[(size_t)NN * DIM];                 // fp32 V (for colsum)
__device__ __nv_bfloat162 g_KV2[(size_t)NN * 256];      // per node: 128 K-pairs then 128 V-pairs (1KB/node)
__device__ float g_partial[64 * DIM];
__device__ float g_colsum[DIM];

// ---------------- packed f32x2 helpers -------------------------------------
union U2 { unsigned long long u; float2 f; };

__device__ __forceinline__ unsigned long long pack2(float x) {
    unsigned long long r;
    unsigned u = __float_as_uint(x);
    asm("mov.b64 %0, {%1, %2};" : "=l"(r) : "r"(u), "r"(u));
    return r;
}

__device__ __forceinline__ void fma2(unsigned long long& d,
                                     unsigned long long a,
                                     unsigned long long b) {
    asm("fma.rn.f32x2 %0, %1, %2, %0;" : "+l"(d) : "l"(a), "l"(b));
}

// ---------------- kernel 1: fused QKV GEMM ---------------------------------
// C[m][n] = sum_k H[m][k] * W[n][k]   (torch Linear: W is [out,in])
// 128x128x16 tiles, 8x8 microtile, packed f32x2 FMA.
// Epilogue: Q -> g_Q (scaled fp32); K -> g_KV2 (bf16); V -> g_V (fp32) + g_KV2 (bf16).
__global__ __launch_bounds__(256, 2)
void qkv_gemm(const float* __restrict__ H,
              const float* __restrict__ Wq,
              const float* __restrict__ Wk,
              const float* __restrict__ Wv) {
    __shared__ float As[16][128];
    __shared__ float Bs[16][128];

    int seg = blockIdx.y >> 1;              // 0=Q 1=K 2=V
    int n0  = (blockIdx.y & 1) * 128;
    int m0  = blockIdx.x * 128;
    const float* W = (seg == 0) ? Wq : (seg == 1) ? Wk : Wv;

    int t  = threadIdx.x;
    int tx = t & 15, ty = t >> 4;
    int lr0 = t >> 2;           // 0..63
    int lc  = (t & 3) * 4;      // 0,4,8,12

    U2 acc[8][4];
    #pragma unroll
    for (int i = 0; i < 8; i++)
        #pragma unroll
        for (int j = 0; j < 4; j++) acc[i][j].u = 0ull;

    for (int kt = 0; kt < DIM; kt += 16) {
        #pragma unroll
        for (int half = 0; half < 2; half++) {
            int r = lr0 + half * 64;
            float4 va = *(const float4*)(H + (size_t)(m0 + r) * DIM + kt + lc);
            As[lc + 0][r] = va.x; As[lc + 1][r] = va.y;
            As[lc + 2][r] = va.z; As[lc + 3][r] = va.w;
            float4 vb = *(const float4*)(W + (size_t)(n0 + r) * DIM + kt + lc);
            Bs[lc + 0][r] = vb.x; Bs[lc + 1][r] = vb.y;
            Bs[lc + 2][r] = vb.z; Bs[lc + 3][r] = vb.w;
        }
        __syncthreads();
        #pragma unroll
        for (int k = 0; k < 16; k++) {
            float4 a0 = *(const float4*)&As[k][ty * 8];
            float4 a1 = *(const float4*)&As[k][ty * 8 + 4];
            const unsigned long long* bp =
                (const unsigned long long*)&Bs[k][tx * 8];
            unsigned long long b0 = bp[0], b1 = bp[1], b2 = bp[2], b3 = bp[3];
            float av[8] = {a0.x, a0.y, a0.z, a0.w, a1.x, a1.y, a1.z, a1.w};
            #pragma unroll
            for (int i = 0; i < 8; i++) {
                unsigned long long ap = pack2(av[i]);
                fma2(acc[i][0].u, ap, b0);
                fma2(acc[i][1].u, ap, b1);
                fma2(acc[i][2].u, ap, b2);
                fma2(acc[i][3].u, ap, b3);
            }
        }
        __syncthreads();
    }

    #pragma unroll
    for (int i = 0; i < 8; i++) {
        int m = m0 + ty * 8 + i;
        int nb = n0 + tx * 8;
        if (seg == 0) {
            float* op = g_Q + (size_t)m * DIM + nb;
            #pragma unroll
            for (int j = 0; j < 4; j++) {
                float2 v = acc[i][j].f;
                v.x *= SCALE; v.y *= SCALE;
                *(float2*)(op + j * 2) = v;
            }
        } else if (seg == 1) {
            __nv_bfloat162* kp = g_KV2 + (size_t)m * 256 + (nb >> 1);
            #pragma unroll
            for (int j = 0; j < 4; j++)
                kp[j] = __float22bfloat162_rn(acc[i][j].f);
        } else {
            float* op = g_V + (size_t)m * DIM + nb;
            __nv_bfloat162* vp = g_KV2 + (size_t)m * 256 + 128 + (nb >> 1);
            #pragma unroll
            for (int j = 0; j < 4; j++) {
                *(float2*)(op + j * 2) = acc[i][j].f;
                vp[j] = __float22bfloat162_rn(acc[i][j].f);
            }
        }
    }
}

// ---------------- kernel 2: column sums of V (deterministic 2-pass) --------
__global__ void colsum_part() {
    int c = threadIdx.x;
    int b = blockIdx.x;
    float s = 0.0f;
    int r0 = b * (NN / 64);
    for (int r = r0; r < r0 + NN / 64; r++)
        s += g_V[(size_t)r * DIM + c];
    g_partial[b * DIM + c] = s;
}

__global__ void colsum_final() {
    int c = threadIdx.x;
    float s = 0.0f;
    #pragma unroll
    for (int b = 0; b < 64; b++) s += g_partial[b * DIM + c];
    g_colsum[c] = s;
}

// ---------------- bf16 dot / accumulate helpers -----------------------------
__device__ __forceinline__ float dot8(float4 q0, float4 q1, uint4 k) {
    const __nv_bfloat162* kb = (const __nv_bfloat162*)&k;
    float2 a = __bfloat1622float2(kb[0]);
    float2 b = __bfloat1622float2(kb[1]);
    float2 c = __bfloat1622float2(kb[2]);
    float2 d = __bfloat1622float2(kb[3]);
    return q0.x * a.x + q0.y * a.y + q0.z * b.x + q0.w * b.y
         + q1.x * c.x + q1.y * c.y + q1.z * d.x + q1.w * d.y;
}

__device__ __forceinline__ void accum8(float* acc, uint4 v, float w) {
    const __nv_bfloat162* vb = (const __nv_bfloat162*)&v;
    float2 a = __bfloat1622float2(vb[0]);
    float2 b = __bfloat1622float2(vb[1]);
    float2 c = __bfloat1622float2(vb[2]);
    float2 d = __bfloat1622float2(vb[3]);
    acc[0] += w * a.x; acc[1] += w * a.y;
    acc[2] += w * b.x; acc[3] += w * b.y;
    acc[4] += w * c.x; acc[5] += w * c.y;
    acc[6] += w * d.x; acc[7] += w * d.y;
}

// ---------------- kernel 3: fused CSR-scan + sparse attention ---------------
// out_i = (colsum(V) + sum_edges expm1(s_ij) * v_j) / (N + sum_edges expm1(s_ij))
// One warp per row. The adj row is scanned in 1024-col chunks (DRAM stream);
// each chunk's edges are gathered immediately (bf16 K||V, 1KB/edge, L2-hot).
// DRAM and L2 phases overlap across warps -> total ~= max(DRAM, L2) time.
__global__ __launch_bounds__(256) void fused_attn(const float* __restrict__ adj,
                                                  float* __restrict__ out) {
    __shared__ int s_cols[8][CHUNK_CAP];

    int w    = threadIdx.x >> 5;
    int lane = threadIdx.x & 31;
    int row  = blockIdx.x * 8 + w;

    const float4* qp = (const float4*)(g_Q + (size_t)row * DIM);
    float4 q0 = qp[lane * 2];        // dims lane*8   .. lane*8+3
    float4 q1 = qp[lane * 2 + 1];    // dims lane*8+4 .. lane*8+7

    float acc[8];
    #pragma unroll
    for (int i = 0; i < 8; i++) acc[i] = 0.0f;
    float dsum = 0.0f;

    const float4* ap = (const float4*)(adj + (size_t)row * NN);
    int* sc = s_cols[w];
    unsigned lt = (1u << lane) - 1u;
    const uint4* kvbase = (const uint4*)g_KV2;

    for (int chunk = 0; chunk < NN / 1024; chunk++) {
        // --- scan 1024 columns: ballot compaction, order-preserving ---
        int cnt = 0;
        #pragma unroll
        for (int it = 0; it < 8; it++) {
            float4 v = ap[chunk * 256 + it * 32 + lane];
            unsigned b0 = __ballot_sync(0xFFFFFFFFu, v.x != 0.0f);
            unsigned b1 = __ballot_sync(0xFFFFFFFFu, v.y != 0.0f);
            unsigned b2 = __ballot_sync(0xFFFFFFFFu, v.z != 0.0f);
            unsigned b3 = __ballot_sync(0xFFFFFFFFu, v.w != 0.0f);
            int pos = cnt + __popc(b0 & lt) + __popc(b1 & lt)
                          + __popc(b2 & lt) + __popc(b3 & lt);
            int j0 = chunk * 1024 + it * 128 + lane * 4;
            if (v.x != 0.0f) { if (pos < CHUNK_CAP) sc[pos] = j0;     pos++; }
            if (v.y != 0.0f) { if (pos < CHUNK_CAP) sc[pos] = j0 + 1; pos++; }
            if (v.z != 0.0f) { if (pos < CHUNK_CAP) sc[pos] = j0 + 2; pos++; }
            if (v.w != 0.0f) { if (pos < CHUNK_CAP) sc[pos] = j0 + 3; pos++; }
            cnt += __popc(b0) + __popc(b1) + __popc(b2) + __popc(b3);
        }
        if (cnt > CHUNK_CAP) cnt = CHUNK_CAP;
        __syncwarp();

        // --- gather: 1KB/edge bf16 K||V, unroll-2 for MLP ---
        int e = 0;
        for (; e + 2 <= cnt; e += 2) {
            int j0 = sc[e], j1 = sc[e + 1];
            const uint4* kv0 = kvbase + (size_t)j0 * 64;
            const uint4* kv1 = kvbase + (size_t)j1 * 64;
            uint4 k0 = kv0[lane], v0 = kv0[32 + lane];
            uint4 k1 = kv1[lane], v1 = kv1[32 + lane];

            float d0 = dot8(q0, q1, k0);
            float d1 = dot8(q0, q1, k1);
            #pragma unroll
            for (int o = 16; o > 0; o >>= 1) {
                d0 += __shfl_xor_sync(0xFFFFFFFFu, d0, o);
                d1 += __shfl_xor_sync(0xFFFFFFFFu, d1, o);
            }
            float w0 = expm1f(d0);
            float w1 = expm1f(d1);
            accum8(acc, v0, w0);
            accum8(acc, v1, w1);
            dsum += w0 + w1;
        }
        if (e < cnt) {
            int j = sc[e];
            const uint4* kv = kvbase + (size_t)j * 64;
            uint4 k = kv[lane], v = kv[32 + lane];
            float d = dot8(q0, q1, k);
            #pragma unroll
            for (int o = 16; o > 0; o >>= 1)
                d += __shfl_xor_sync(0xFFFFFFFFu, d, o);
            float wv = expm1f(d);
            accum8(acc, v, wv);
            dsum += wv;
        }
        __syncwarp();   // sc reuse next chunk
    }

    float inv = 1.0f / ((float)NN + dsum);
    const float4* cs = (const float4*)g_colsum;
    float4 c0 = cs[lane * 2], c1 = cs[lane * 2 + 1];

    float4* op = (float4*)(out + (size_t)row * DIM + lane * 8);
    op[0] = make_float4((c0.x + acc[0]) * inv, (c0.y + acc[1]) * inv,
                        (c0.z + acc[2]) * inv, (c0.w + acc[3]) * inv);
    op[1] = make_float4((c1.x + acc[4]) * inv, (c1.y + acc[5]) * inv,
                        (c1.z + acc[6]) * inv, (c1.w + acc[7]) * inv);
}

// ---------------- launcher --------------------------------------------------
extern "C" void kernel_launch(void* const* d_in, const int* in_sizes, int n_in,
                              void* d_out, int out_size) {
    const float* adj = (const float*)d_in[0];
    const float* h   = (const float*)d_in[1];
    const float* Wq  = (const float*)d_in[2];
    const float* Wk  = (const float*)d_in[3];
    const float* Wv  = (const float*)d_in[4];
    float* out = (float*)d_out;

    qkv_gemm<<<dim3(NN / 128, 6), 256>>>(h, Wq, Wk, Wv);
    colsum_part<<<64, 256>>>();
    colsum_final<<<1, 256>>>();
    fused_attn<<<NN / 8, 256>>>(adj, out);
}

// round 8
// speedup vs baseline: 1.1047x; 1.1047x over previous
#include <cuda_runtime.h>
#include <cuda_fp16.h>
#include <math.h>

// Problem constants
#define NN        8192      // nodes
#define DIM       256       // in_dim == out_dim
#define SCALE     0.0625f   // 1/sqrt(256)
#define CHUNK_CAP 64        // per-1024-col chunk edge cap (mean ~10, P(>63) ~ 1e-30)

// ---------------- scratch (static device memory; no allocs allowed) --------
__device__ float g_Q[(size_t)NN * DIM];            // SCALE * Q, fp32
__device__ float g_V[(size_t)NN * DIM];            // fp32 V (for colsum)
__device__ __half2 g_KV2[(size_t)NN * 256];        // per node: 128 K-half2 then 128 V-half2 (1KB/node)
__device__ float g_partial[64 * DIM];
__device__ float g_colsum[DIM];

// ---------------- packed f32x2 helpers -------------------------------------
union U2 { unsigned long long u; float2 f; };

__device__ __forceinline__ unsigned long long pack2(float x) {
    unsigned long long r;
    unsigned u = __float_as_uint(x);
    asm("mov.b64 %0, {%1, %2};" : "=l"(r) : "r"(u), "r"(u));
    return r;
}

__device__ __forceinline__ void fma2(unsigned long long& d,
                                     unsigned long long a,
                                     unsigned long long b) {
    asm("fma.rn.f32x2 %0, %1, %2, %0;" : "+l"(d) : "l"(a), "l"(b));
}

// ---------------- kernel 1: fused QKV GEMM ---------------------------------
// C[m][n] = sum_k H[m][k] * W[n][k]   (torch Linear: W is [out,in])
// 128x128x16 tiles, 8x8 microtile, packed f32x2 FMA.
// Epilogue: Q -> g_Q (scaled fp32); K -> g_KV2 (fp16); V -> g_V (fp32) + g_KV2 (fp16).
__global__ __launch_bounds__(256, 2)
void qkv_gemm(const float* __restrict__ H,
              const float* __restrict__ Wq,
              const float* __restrict__ Wk,
              const float* __restrict__ Wv) {
    __shared__ float As[16][128];
    __shared__ float Bs[16][128];

    int seg = blockIdx.y >> 1;              // 0=Q 1=K 2=V
    int n0  = (blockIdx.y & 1) * 128;
    int m0  = blockIdx.x * 128;
    const float* W = (seg == 0) ? Wq : (seg == 1) ? Wk : Wv;

    int t  = threadIdx.x;
    int tx = t & 15, ty = t >> 4;
    int lr0 = t >> 2;           // 0..63
    int lc  = (t & 3) * 4;      // 0,4,8,12

    U2 acc[8][4];
    #pragma unroll
    for (int i = 0; i < 8; i++)
        #pragma unroll
        for (int j = 0; j < 4; j++) acc[i][j].u = 0ull;

    for (int kt = 0; kt < DIM; kt += 16) {
        #pragma unroll
        for (int half = 0; half < 2; half++) {
            int r = lr0 + half * 64;
            float4 va = *(const float4*)(H + (size_t)(m0 + r) * DIM + kt + lc);
            As[lc + 0][r] = va.x; As[lc + 1][r] = va.y;
            As[lc + 2][r] = va.z; As[lc + 3][r] = va.w;
            float4 vb = *(const float4*)(W + (size_t)(n0 + r) * DIM + kt + lc);
            Bs[lc + 0][r] = vb.x; Bs[lc + 1][r] = vb.y;
            Bs[lc + 2][r] = vb.z; Bs[lc + 3][r] = vb.w;
        }
        __syncthreads();
        #pragma unroll
        for (int k = 0; k < 16; k++) {
            float4 a0 = *(const float4*)&As[k][ty * 8];
            float4 a1 = *(const float4*)&As[k][ty * 8 + 4];
            const unsigned long long* bp =
                (const unsigned long long*)&Bs[k][tx * 8];
            unsigned long long b0 = bp[0], b1 = bp[1], b2 = bp[2], b3 = bp[3];
            float av[8] = {a0.x, a0.y, a0.z, a0.w, a1.x, a1.y, a1.z, a1.w};
            #pragma unroll
            for (int i = 0; i < 8; i++) {
                unsigned long long ap = pack2(av[i]);
                fma2(acc[i][0].u, ap, b0);
                fma2(acc[i][1].u, ap, b1);
                fma2(acc[i][2].u, ap, b2);
                fma2(acc[i][3].u, ap, b3);
            }
        }
        __syncthreads();
    }

    #pragma unroll
    for (int i = 0; i < 8; i++) {
        int m = m0 + ty * 8 + i;
        int nb = n0 + tx * 8;
        if (seg == 0) {
            float* op = g_Q + (size_t)m * DIM + nb;
            #pragma unroll
            for (int j = 0; j < 4; j++) {
                float2 v = acc[i][j].f;
                v.x *= SCALE; v.y *= SCALE;
                *(float2*)(op + j * 2) = v;
            }
        } else if (seg == 1) {
            __half2* kp = g_KV2 + (size_t)m * 256 + (nb >> 1);
            #pragma unroll
            for (int j = 0; j < 4; j++)
                kp[j] = __float22half2_rn(acc[i][j].f);
        } else {
            float* op = g_V + (size_t)m * DIM + nb;
            __half2* vp = g_KV2 + (size_t)m * 256 + 128 + (nb >> 1);
            #pragma unroll
            for (int j = 0; j < 4; j++) {
                *(float2*)(op + j * 2) = acc[i][j].f;
                vp[j] = __float22half2_rn(acc[i][j].f);
            }
        }
    }
}

// ---------------- kernel 2: column sums of V (deterministic 2-pass) --------
__global__ void colsum_part() {
    int c = threadIdx.x;
    int b = blockIdx.x;
    float s = 0.0f;
    int r0 = b * (NN / 64);
    for (int r = r0; r < r0 + NN / 64; r++)
        s += g_V[(size_t)r * DIM + c];
    g_partial[b * DIM + c] = s;
}

__global__ void colsum_final() {
    int c = threadIdx.x;
    float s = 0.0f;
    #pragma unroll
    for (int b = 0; b < 64; b++) s += g_partial[b * DIM + c];
    g_colsum[c] = s;
}

// ---------------- fp16 dot / accumulate helpers -----------------------------
__device__ __forceinline__ float dot8h(float4 q0, float4 q1, uint4 k) {
    const __half2* kb = (const __half2*)&k;
    float2 a = __half22float2(kb[0]);
    float2 b = __half22float2(kb[1]);
    float2 c = __half22float2(kb[2]);
    float2 d = __half22float2(kb[3]);
    return q0.x * a.x + q0.y * a.y + q0.z * b.x + q0.w * b.y
         + q1.x * c.x + q1.y * c.y + q1.z * d.x + q1.w * d.y;
}

__device__ __forceinline__ void accum8h(float* acc, uint4 v, float w) {
    const __half2* vb = (const __half2*)&v;
    float2 a = __half22float2(vb[0]);
    float2 b = __half22float2(vb[1]);
    float2 c = __half22float2(vb[2]);
    float2 d = __half22float2(vb[3]);
    acc[0] += w * a.x; acc[1] += w * a.y;
    acc[2] += w * b.x; acc[3] += w * b.y;
    acc[4] += w * c.x; acc[5] += w * c.y;
    acc[6] += w * d.x; acc[7] += w * d.y;
}

// ---------------- kernel 3: fused scan + sparse attention -------------------
// out_i = (colsum(V) + sum_edges expm1(s_ij) * v_j) / (N + sum_edges expm1(s_ij))
// TWO warps per row (each owns half the columns). Per 1024-col chunk: each
// lane owns 32 contiguous columns, front-loads all 8 uint4 (MLP=8 on the adj
// DRAM stream), builds a 32-bit nonzero mask, one warp prefix-scan produces
// ordered edge list in smem; gather (fp16 K||V, 1KB/edge, L2-hot) follows.
__global__ __launch_bounds__(128) void fused_attn(const float* __restrict__ adj,
                                                  float* __restrict__ out) {
    __shared__ int   s_cols[4][CHUNK_CAP];
    __shared__ float s_acc[2][32][8];
    __shared__ float s_dsum[2];

    int w    = threadIdx.x >> 5;     // 0..3
    int lane = threadIdx.x & 31;
    int rib  = w >> 1;               // row in block: 0,1
    int half = w & 1;                // column half: 0,1
    int row  = blockIdx.x * 2 + rib;

    const float4* qp = (const float4*)(g_Q + (size_t)row * DIM);
    float4 q0 = qp[lane * 2];        // dims lane*8   .. lane*8+3
    float4 q1 = qp[lane * 2 + 1];    // dims lane*8+4 .. lane*8+7

    float acc[8];
    #pragma unroll
    for (int i = 0; i < 8; i++) acc[i] = 0.0f;
    float dsum = 0.0f;

    int* sc = s_cols[w];
    const uint4* kvbase = (const uint4*)g_KV2;

    for (int chunk = 0; chunk < 4; chunk++) {
        int colBase = half * (NN / 2) + chunk * 1024;
        // --- front-load 8 uint4 = lane's 32 contiguous columns ---
        const uint4* L = (const uint4*)(adj + (size_t)row * NN + colBase) + lane * 8;
        uint4 r0 = L[0], r1 = L[1], r2 = L[2], r3 = L[3];
        uint4 r4 = L[4], r5 = L[5], r6 = L[6], r7 = L[7];

        unsigned m = 0;
        m |= (r0.x?1u:0u)      | (r0.y?2u:0u)       | (r0.z?4u:0u)       | (r0.w?8u:0u);
        m |= (r1.x?16u:0u)     | (r1.y?32u:0u)      | (r1.z?64u:0u)      | (r1.w?128u:0u);
        m |= (r2.x?256u:0u)    | (r2.y?512u:0u)     | (r2.z?1024u:0u)    | (r2.w?2048u:0u);
        m |= (r3.x?4096u:0u)   | (r3.y?8192u:0u)    | (r3.z?16384u:0u)   | (r3.w?32768u:0u);
        m |= (r4.x?(1u<<16):0u)| (r4.y?(1u<<17):0u) | (r4.z?(1u<<18):0u) | (r4.w?(1u<<19):0u);
        m |= (r5.x?(1u<<20):0u)| (r5.y?(1u<<21):0u) | (r5.z?(1u<<22):0u) | (r5.w?(1u<<23):0u);
        m |= (r6.x?(1u<<24):0u)| (r6.y?(1u<<25):0u) | (r6.z?(1u<<26):0u) | (r6.w?(1u<<27):0u);
        m |= (r7.x?(1u<<28):0u)| (r7.y?(1u<<29):0u) | (r7.z?(1u<<30):0u) | (r7.w?(1u<<31):0u);

        int cnt  = __popc(m);
        int incl = cnt;
        #pragma unroll
        for (int o = 1; o < 32; o <<= 1) {
            int n = __shfl_up_sync(0xFFFFFFFFu, incl, o);
            if (lane >= o) incl += n;
        }
        int pos   = incl - cnt;
        int total = __shfl_sync(0xFFFFFFFFu, incl, 31);

        int myBase = colBase + lane * 32;
        unsigned mm = m;
        while (mm) {
            int b = __ffs(mm) - 1;
            mm &= mm - 1;
            if (pos < CHUNK_CAP) sc[pos] = myBase + b;
            pos++;
        }
        if (total > CHUNK_CAP) total = CHUNK_CAP;
        __syncwarp();

        // --- gather: 1KB/edge fp16 K||V, unroll-2 for MLP ---
        int e = 0;
        for (; e + 2 <= total; e += 2) {
            int j0 = sc[e], j1 = sc[e + 1];
            const uint4* kv0 = kvbase + (size_t)j0 * 64;
            const uint4* kv1 = kvbase + (size_t)j1 * 64;
            uint4 k0 = kv0[lane], v0 = kv0[32 + lane];
            uint4 k1 = kv1[lane], v1 = kv1[32 + lane];

            float d0 = dot8h(q0, q1, k0);
            float d1 = dot8h(q0, q1, k1);
            #pragma unroll
            for (int o = 16; o > 0; o >>= 1) {
                d0 += __shfl_xor_sync(0xFFFFFFFFu, d0, o);
                d1 += __shfl_xor_sync(0xFFFFFFFFu, d1, o);
            }
            float w0 = expm1f(d0);
            float w1 = expm1f(d1);
            accum8h(acc, v0, w0);
            accum8h(acc, v1, w1);
            dsum += w0 + w1;
        }
        if (e < total) {
            int j = sc[e];
            const uint4* kv = kvbase + (size_t)j * 64;
            uint4 k = kv[lane], v = kv[32 + lane];
            float d = dot8h(q0, q1, k);
            #pragma unroll
            for (int o = 16; o > 0; o >>= 1)
                d += __shfl_xor_sync(0xFFFFFFFFu, d, o);
            float wv = expm1f(d);
            accum8h(acc, v, wv);
            dsum += wv;
        }
        __syncwarp();   // sc reuse next chunk
    }

    // --- combine the two half-row warps ---
    if (half == 1) {
        #pragma unroll
        for (int i = 0; i < 8; i++) s_acc[rib][lane][i] = acc[i];
        if (lane == 0) s_dsum[rib] = dsum;
    }
    __syncthreads();
    if (half == 0) {
        #pragma unroll
        for (int i = 0; i < 8; i++) acc[i] += s_acc[rib][lane][i];
        dsum += s_dsum[rib];

        float inv = 1.0f / ((float)NN + dsum);
        const float4* cs = (const float4*)g_colsum;
        float4 c0 = cs[lane * 2], c1 = cs[lane * 2 + 1];

        float4* op = (float4*)(out + (size_t)row * DIM + lane * 8);
        op[0] = make_float4((c0.x + acc[0]) * inv, (c0.y + acc[1]) * inv,
                            (c0.z + acc[2]) * inv, (c0.w + acc[3]) * inv);
        op[1] = make_float4((c1.x + acc[4]) * inv, (c1.y + acc[5]) * inv,
                            (c1.z + acc[6]) * inv, (c1.w + acc[7]) * inv);
    }
}

// ---------------- launcher --------------------------------------------------
extern "C" void kernel_launch(void* const* d_in, const int* in_sizes, int n_in,
                              void* d_out, int out_size) {
    const float* adj = (const float*)d_in[0];
    const float* h   = (const float*)d_in[1];
    const float* Wq  = (const float*)d_in[2];
    const float* Wk  = (const float*)d_in[3];
    const float* Wv  = (const float*)d_in[4];
    float* out = (float*)d_out;

    qkv_gemm<<<dim3(NN / 128, 6), 256>>>(h, Wq, Wk, Wv);
    colsum_part<<<64, 256>>>();
    colsum_final<<<1, 256>>>();
    fused_attn<<<NN / 2, 128>>>(adj, out);
}

// round 11
// speedup vs baseline: 1.5378x; 1.3921x over previous
#include <cuda_runtime.h>
#include <cuda_fp16.h>
#include <mma.h>
#include <math.h>

using namespace nvcuda;

// Problem constants
#define NN        8192      // nodes
#define DIM       256       // in_dim == out_dim
#define SCALE     0.0625f   // 1/sqrt(256)
#define CHUNK_CAP 64        // per-1024-col chunk edge cap (mean ~10, P(>63) ~ 1e-30)

// ---------------- scratch (static device memory; no allocs allowed) --------
__device__ float  g_Q[(size_t)NN * DIM];           // SCALE * Q, fp32
__device__ float  g_K32[(size_t)NN * DIM];         // fp32 K (staging)
__device__ float  g_V[(size_t)NN * DIM];           // fp32 V (for colsum)
__device__ __half g_Hh[(size_t)NN * DIM];          // fp16 H
__device__ __half g_Wh[3 * DIM * DIM];             // fp16 Wq|Wk|Wv
__device__ __half2 g_KV2[(size_t)NN * 256];        // per node: 128 K-half2 then 128 V-half2 (1KB/node)
__device__ float  g_partial[64 * DIM];
__device__ float  g_colsum[DIM];

// ---------------- kernel 0: fp32 -> fp16 input conversion ------------------
#define NH  (NN * DIM)            // 2,097,152
#define NW  (DIM * DIM)           // 65,536
__global__ void convert_inputs(const float* __restrict__ H,
                               const float* __restrict__ Wq,
                               const float* __restrict__ Wk,
                               const float* __restrict__ Wv) {
    int i = blockIdx.x * blockDim.x + threadIdx.x;
    if (i < NH) {
        g_Hh[i] = __float2half(H[i]);
    } else {
        int j = i - NH;
        if (j < 3 * NW) {
            int seg = j / NW, r = j % NW;
            const float* W = (seg == 0) ? Wq : (seg == 1) ? Wk : Wv;
            g_Wh[j] = __float2half(W[r]);
        }
    }
}

// ---------------- kernel 1: wmma fp16 GEMM (fp32 accumulate) ----------------
// C[m][n] = sum_k Hh[m][k] * Wh[n][k]. 128x128 block tile, 8 warps of 64x32,
// K-step 32 through smem. B (W, row-major [N][K]) is read as col_major [K][N].
#define BK   32
#define LDS_ 48     // smem leading dim (halfs); 96B rows keep uint4 alignment
__global__ __launch_bounds__(256)
void wmma_gemm() {
    __shared__ __half As[128 * LDS_];
    __shared__ __half Bs[128 * LDS_];

    int seg = blockIdx.z;                   // 0=Q 1=K 2=V
    int m0  = blockIdx.x * 128;
    int n0  = blockIdx.y * 128;
    const __half* A = g_Hh;
    const __half* B = g_Wh + (size_t)seg * NW;
    float* Out = (seg == 0) ? g_Q : (seg == 1) ? g_K32 : g_V;

    int t    = threadIdx.x;
    int wid  = t >> 5;
    int wm   = wid & 1;                     // 0..1  (64-row slabs)
    int wn   = wid >> 1;                    // 0..3  (32-col slabs)

    wmma::fragment<wmma::accumulator, 16, 16, 16, float> c[4][2];
    #pragma unroll
    for (int i = 0; i < 4; i++)
        #pragma unroll
        for (int j = 0; j < 2; j++)
            wmma::fill_fragment(c[i][j], 0.0f);

    // each thread copies 2 uint4 (= 16 halfs) of A and of B per k-tile
    int ldr = t >> 2;          // 0..63  (row pair base)
    int ldq = t & 3;           // 16B chunk within 32-half row

    for (int kt = 0; kt < DIM; kt += BK) {
        #pragma unroll
        for (int h = 0; h < 2; h++) {
            int row = ldr + h * 64;
            *(uint4*)&As[row * LDS_ + ldq * 8] =
                *(const uint4*)&A[(size_t)(m0 + row) * DIM + kt + ldq * 8];
            *(uint4*)&Bs[row * LDS_ + ldq * 8] =
                *(const uint4*)&B[(size_t)(n0 + row) * DIM + kt + ldq * 8];
        }
        __syncthreads();

        #pragma unroll
        for (int kk = 0; kk < BK; kk += 16) {
            wmma::fragment<wmma::matrix_a, 16, 16, 16, __half, wmma::row_major> a[4];
            wmma::fragment<wmma::matrix_b, 16, 16, 16, __half, wmma::col_major> b[2];
            #pragma unroll
            for (int i = 0; i < 4; i++)
                wmma::load_matrix_sync(a[i], &As[(wm * 64 + i * 16) * LDS_ + kk], LDS_);
            #pragma unroll
            for (int j = 0; j < 2; j++)
                wmma::load_matrix_sync(b[j], &Bs[(wn * 32 + j * 16) * LDS_ + kk], LDS_);
            #pragma unroll
            for (int i = 0; i < 4; i++)
                #pragma unroll
                for (int j = 0; j < 2; j++)
                    wmma::mma_sync(c[i][j], a[i], b[j], c[i][j]);
        }
        __syncthreads();
    }

    if (seg == 0) {   // fold attention scale into Q
        #pragma unroll
        for (int i = 0; i < 4; i++)
            #pragma unroll
            for (int j = 0; j < 2; j++)
                #pragma unroll
                for (int e = 0; e < c[i][j].num_elements; e++)
                    c[i][j].x[e] *= SCALE;
    }

    #pragma unroll
    for (int i = 0; i < 4; i++)
        #pragma unroll
        for (int j = 0; j < 2; j++)
            wmma::store_matrix_sync(
                &Out[(size_t)(m0 + wm * 64 + i * 16) * DIM + n0 + wn * 32 + j * 16],
                c[i][j], DIM, wmma::mem_row_major);
}

// ---------------- kernel 2: pack K,V into fp16 K||V node layout -------------
__global__ void pack_kv() {
    int m = blockIdx.x;
    int t = threadIdx.x;          // 0..255
    if (t < 128) {
        float2 k = ((const float2*)(g_K32 + (size_t)m * DIM))[t];
        g_KV2[(size_t)m * 256 + t] = __float22half2_rn(k);
    } else {
        float2 v = ((const float2*)(g_V + (size_t)m * DIM))[t - 128];
        g_KV2[(size_t)m * 256 + t] = __float22half2_rn(v);
    }
}

// ---------------- kernel 3: column sums of V (deterministic 2-pass) --------
__global__ void colsum_part() {
    int c = threadIdx.x;
    int b = blockIdx.x;
    float s = 0.0f;
    int r0 = b * (NN / 64);
    for (int r = r0; r < r0 + NN / 64; r++)
        s += g_V[(size_t)r * DIM + c];
    g_partial[b * DIM + c] = s;
}

__global__ void colsum_final() {
    int c = threadIdx.x;
    float s = 0.0f;
    #pragma unroll
    for (int b = 0; b < 64; b++) s += g_partial[b * DIM + c];
    g_colsum[c] = s;
}

// ---------------- fp16 dot / accumulate helpers -----------------------------
__device__ __forceinline__ float dot8h(float4 q0, float4 q1, uint4 k) {
    const __half2* kb = (const __half2*)&k;
    float2 a = __half22float2(kb[0]);
    float2 b = __half22float2(kb[1]);
    float2 c = __half22float2(kb[2]);
    float2 d = __half22float2(kb[3]);
    return q0.x * a.x + q0.y * a.y + q0.z * b.x + q0.w * b.y
         + q1.x * c.x + q1.y * c.y + q1.z * d.x + q1.w * d.y;
}

__device__ __forceinline__ void accum8h(float* acc, uint4 v, float w) {
    const __half2* vb = (const __half2*)&v;
    float2 a = __half22float2(vb[0]);
    float2 b = __half22float2(vb[1]);
    float2 c = __half22float2(vb[2]);
    float2 d = __half22float2(vb[3]);
    acc[0] += w * a.x; acc[1] += w * a.y;
    acc[2] += w * b.x; acc[3] += w * b.y;
    acc[4] += w * c.x; acc[5] += w * c.y;
    acc[6] += w * d.x; acc[7] += w * d.y;
}

// ---------------- kernel 4: fused scan + sparse attention -------------------
// out_i = (colsum(V) + sum_edges expm1(s_ij) * v_j) / (N + sum_edges expm1(s_ij))
// TWO warps per row (each owns half the columns). Per 1024-col chunk: each
// lane owns 32 contiguous columns, front-loads all 8 uint4 (MLP=8 on the adj
// DRAM stream), builds a 32-bit nonzero mask, one warp prefix-scan produces
// ordered edge list in smem; gather (fp16 K||V, 1KB/edge, L2-hot) follows.
__global__ __launch_bounds__(128) void fused_attn(const float* __restrict__ adj,
                                                  float* __restrict__ out) {
    __shared__ int   s_cols[4][CHUNK_CAP];
    __shared__ float s_acc[2][32][8];
    __shared__ float s_dsum[2];

    int w    = threadIdx.x >> 5;     // 0..3
    int lane = threadIdx.x & 31;
    int rib  = w >> 1;               // row in block: 0,1
    int half = w & 1;                // column half: 0,1
    int row  = blockIdx.x * 2 + rib;

    const float4* qp = (const float4*)(g_Q + (size_t)row * DIM);
    float4 q0 = qp[lane * 2];        // dims lane*8   .. lane*8+3
    float4 q1 = qp[lane * 2 + 1];    // dims lane*8+4 .. lane*8+7

    float acc[8];
    #pragma unroll
    for (int i = 0; i < 8; i++) acc[i] = 0.0f;
    float dsum = 0.0f;

    int* sc = s_cols[w];
    const uint4* kvbase = (const uint4*)g_KV2;

    for (int chunk = 0; chunk < 4; chunk++) {
        int colBase = half * (NN / 2) + chunk * 1024;
        // --- front-load 8 uint4 = lane's 32 contiguous columns ---
        const uint4* L = (const uint4*)(adj + (size_t)row * NN + colBase) + lane * 8;
        uint4 r0 = L[0], r1 = L[1], r2 = L[2], r3 = L[3];
        uint4 r4 = L[4], r5 = L[5], r6 = L[6], r7 = L[7];

        unsigned m = 0;
        m |= (r0.x?1u:0u)      | (r0.y?2u:0u)       | (r0.z?4u:0u)       | (r0.w?8u:0u);
        m |= (r1.x?16u:0u)     | (r1.y?32u:0u)      | (r1.z?64u:0u)      | (r1.w?128u:0u);
        m |= (r2.x?256u:0u)    | (r2.y?512u:0u)     | (r2.z?1024u:0u)    | (r2.w?2048u:0u);
        m |= (r3.x?4096u:0u)   | (r3.y?8192u:0u)    | (r3.z?16384u:0u)   | (r3.w?32768u:0u);
        m |= (r4.x?(1u<<16):0u)| (r4.y?(1u<<17):0u) | (r4.z?(1u<<18):0u) | (r4.w?(1u<<19):0u);
        m |= (r5.x?(1u<<20):0u)| (r5.y?(1u<<21):0u) | (r5.z?(1u<<22):0u) | (r5.w?(1u<<23):0u);
        m |= (r6.x?(1u<<24):0u)| (r6.y?(1u<<25):0u) | (r6.z?(1u<<26):0u) | (r6.w?(1u<<27):0u);
        m |= (r7.x?(1u<<28):0u)| (r7.y?(1u<<29):0u) | (r7.z?(1u<<30):0u) | (r7.w?(1u<<31):0u);

        int cnt  = __popc(m);
        int incl = cnt;
        #pragma unroll
        for (int o = 1; o < 32; o <<= 1) {
            int n = __shfl_up_sync(0xFFFFFFFFu, incl, o);
            if (lane >= o) incl += n;
        }
        int pos   = incl - cnt;
        int total = __shfl_sync(0xFFFFFFFFu, incl, 31);

        int myBase = colBase + lane * 32;
        unsigned mm = m;
        while (mm) {
            int b = __ffs(mm) - 1;
            mm &= mm - 1;
            if (pos < CHUNK_CAP) sc[pos] = myBase + b;
            pos++;
        }
        if (total > CHUNK_CAP) total = CHUNK_CAP;
        __syncwarp();

        // --- gather: 1KB/edge fp16 K||V, unroll-2 for MLP ---
        int e = 0;
        for (; e + 2 <= total; e += 2) {
            int j0 = sc[e], j1 = sc[e + 1];
            const uint4* kv0 = kvbase + (size_t)j0 * 64;
            const uint4* kv1 = kvbase + (size_t)j1 * 64;
            uint4 k0 = kv0[lane], v0 = kv0[32 + lane];
            uint4 k1 = kv1[lane], v1 = kv1[32 + lane];

            float d0 = dot8h(q0, q1, k0);
            float d1 = dot8h(q0, q1, k1);
            #pragma unroll
            for (int o = 16; o > 0; o >>= 1) {
                d0 += __shfl_xor_sync(0xFFFFFFFFu, d0, o);
                d1 += __shfl_xor_sync(0xFFFFFFFFu, d1, o);
            }
            float w0 = expm1f(d0);
            float w1 = expm1f(d1);
            accum8h(acc, v0, w0);
            accum8h(acc, v1, w1);
            dsum += w0 + w1;
        }
        if (e < total) {
            int j = sc[e];
            const uint4* kv = kvbase + (size_t)j * 64;
            uint4 k = kv[lane], v = kv[32 + lane];
            float d = dot8h(q0, q1, k);
            #pragma unroll
            for (int o = 16; o > 0; o >>= 1)
                d += __shfl_xor_sync(0xFFFFFFFFu, d, o);
            float wv = expm1f(d);
            accum8h(acc, v, wv);
            dsum += wv;
        }
        __syncwarp();   // sc reuse next chunk
    }

    // --- combine the two half-row warps ---
    if (half == 1) {
        #pragma unroll
        for (int i = 0; i < 8; i++) s_acc[rib][lane][i] = acc[i];
        if (lane == 0) s_dsum[rib] = dsum;
    }
    __syncthreads();
    if (half == 0) {
        #pragma unroll
        for (int i = 0; i < 8; i++) acc[i] += s_acc[rib][lane][i];
        dsum += s_dsum[rib];

        float inv = 1.0f / ((float)NN + dsum);
        const float4* cs = (const float4*)g_colsum;
        float4 c0 = cs[lane * 2], c1 = cs[lane * 2 + 1];

        float4* op = (float4*)(out + (size_t)row * DIM + lane * 8);
        op[0] = make_float4((c0.x + acc[0]) * inv, (c0.y + acc[1]) * inv,
                            (c0.z + acc[2]) * inv, (c0.w + acc[3]) * inv);
        op[1] = make_float4((c1.x + acc[4]) * inv, (c1.y + acc[5]) * inv,
                            (c1.z + acc[6]) * inv, (c1.w + acc[7]) * inv);
    }
}

// ---------------- launcher --------------------------------------------------
extern "C" void kernel_launch(void* const* d_in, const int* in_sizes, int n_in,
                              void* d_out, int out_size) {
    const float* adj = (const float*)d_in[0];
    const float* h   = (const float*)d_in[1];
    const float* Wq  = (const float*)d_in[2];
    const float* Wk  = (const float*)d_in[3];
    const float* Wv  = (const float*)d_in[4];
    float* out = (float*)d_out;

    int tot = NH + 3 * NW;
    convert_inputs<<<(tot + 255) / 256, 256>>>(h, Wq, Wk, Wv);
    wmma_gemm<<<dim3(NN / 128, DIM / 128, 3), 256>>>();
    pack_kv<<<NN, 256>>>();
    colsum_part<<<64, 256>>>();
    colsum_final<<<1, 256>>>();
    fused_attn<<<NN / 2, 128>>>(adj, out);
}

// round 14
// speedup vs baseline: 1.6368x; 1.0644x over previous
#include <cuda_runtime.h>
#include <cuda_fp16.h>
#include <mma.h>
#include <math.h>
#include <cstdint>

using namespace nvcuda;

// Problem constants
#define NN        8192      // nodes
#define DIM       256       // in_dim == out_dim
#define SCALE     0.0625f   // 1/sqrt(256)
#define ACHUNK    512       // adj cols per pipelined chunk
#define NCHUNK    8         // chunks per half-row = 4096/512
#define CHUNK_CAP 48        // per-512-col chunk edge cap (mean ~5.1)

// ---------------- scratch (static device memory; no allocs allowed) --------
__device__ float  g_Q[(size_t)NN * DIM];           // SCALE * Q, fp32
__device__ float  g_K32[(size_t)NN * DIM];         // fp32 K (staging)
__device__ float  g_V[(size_t)NN * DIM];           // fp32 V (for colsum)
__device__ __half g_Hh[(size_t)NN * DIM];          // fp16 H
__device__ __half g_Wh[3 * DIM * DIM];             // fp16 Wq|Wk|Wv
__device__ __half2 g_KV2[(size_t)NN * 256];        // per node: 128 K-half2 then 128 V-half2 (1KB/node)
__device__ float  g_partial[64 * DIM];
__device__ float  g_colsum[DIM];

// ---------------- kernel 0: fp32 -> fp16 input conversion ------------------
#define NH  (NN * DIM)            // 2,097,152
#define NW  (DIM * DIM)           // 65,536
__global__ void convert_inputs(const float* __restrict__ H,
                               const float* __restrict__ Wq,
                               const float* __restrict__ Wk,
                               const float* __restrict__ Wv) {
    int i = blockIdx.x * blockDim.x + threadIdx.x;
    if (i < NH) {
        g_Hh[i] = __float2half(H[i]);
    } else {
        int j = i - NH;
        if (j < 3 * NW) {
            int seg = j / NW, r = j % NW;
            const float* W = (seg == 0) ? Wq : (seg == 1) ? Wk : Wv;
            g_Wh[j] = __float2half(W[r]);
        }
    }
}

// ---------------- kernel 1: wmma fp16 GEMM (fp32 accumulate) ----------------
// C[m][n] = sum_k Hh[m][k] * Wh[n][k]. 128x128 block tile, 8 warps of 64x32,
// K-step 32 through smem. B (W, row-major [N][K]) is read as col_major [K][N].
#define BK   32
#define LDS_ 48     // smem leading dim (halfs); 96B rows keep uint4 alignment
__global__ __launch_bounds__(256)
void wmma_gemm() {
    __shared__ __half As[128 * LDS_];
    __shared__ __half Bs[128 * LDS_];

    int seg = blockIdx.z;                   // 0=Q 1=K 2=V
    int m0  = blockIdx.x * 128;
    int n0  = blockIdx.y * 128;
    const __half* A = g_Hh;
    const __half* B = g_Wh + (size_t)seg * NW;
    float* Out = (seg == 0) ? g_Q : (seg == 1) ? g_K32 : g_V;

    int t    = threadIdx.x;
    int wid  = t >> 5;
    int wm   = wid & 1;                     // 0..1  (64-row slabs)
    int wn   = wid >> 1;                    // 0..3  (32-col slabs)

    wmma::fragment<wmma::accumulator, 16, 16, 16, float> c[4][2];
    #pragma unroll
    for (int i = 0; i < 4; i++)
        #pragma unroll
        for (int j = 0; j < 2; j++)
            wmma::fill_fragment(c[i][j], 0.0f);

    // each thread copies 2 uint4 (= 16 halfs) of A and of B per k-tile
    int ldr = t >> 2;          // 0..63  (row pair base)
    int ldq = t & 3;           // 16B chunk within 32-half row

    for (int kt = 0; kt < DIM; kt += BK) {
        #pragma unroll
        for (int h = 0; h < 2; h++) {
            int row = ldr + h * 64;
            *(uint4*)&As[row * LDS_ + ldq * 8] =
                *(const uint4*)&A[(size_t)(m0 + row) * DIM + kt + ldq * 8];
            *(uint4*)&Bs[row * LDS_ + ldq * 8] =
                *(const uint4*)&B[(size_t)(n0 + row) * DIM + kt + ldq * 8];
        }
        __syncthreads();

        #pragma unroll
        for (int kk = 0; kk < BK; kk += 16) {
            wmma::fragment<wmma::matrix_a, 16, 16, 16, __half, wmma::row_major> a[4];
            wmma::fragment<wmma::matrix_b, 16, 16, 16, __half, wmma::col_major> b[2];
            #pragma unroll
            for (int i = 0; i < 4; i++)
                wmma::load_matrix_sync(a[i], &As[(wm * 64 + i * 16) * LDS_ + kk], LDS_);
            #pragma unroll
            for (int j = 0; j < 2; j++)
                wmma::load_matrix_sync(b[j], &Bs[(wn * 32 + j * 16) * LDS_ + kk], LDS_);
            #pragma unroll
            for (int i = 0; i < 4; i++)
                #pragma unroll
                for (int j = 0; j < 2; j++)
                    wmma::mma_sync(c[i][j], a[i], b[j], c[i][j]);
        }
        __syncthreads();
    }

    if (seg == 0) {   // fold attention scale into Q
        #pragma unroll
        for (int i = 0; i < 4; i++)
            #pragma unroll
            for (int j = 0; j < 2; j++)
                #pragma unroll
                for (int e = 0; e < c[i][j].num_elements; e++)
                    c[i][j].x[e] *= SCALE;
    }

    #pragma unroll
    for (int i = 0; i < 4; i++)
        #pragma unroll
        for (int j = 0; j < 2; j++)
            wmma::store_matrix_sync(
                &Out[(size_t)(m0 + wm * 64 + i * 16) * DIM + n0 + wn * 32 + j * 16],
                c[i][j], DIM, wmma::mem_row_major);
}

// ---------------- kernel 2: pack K,V into fp16 K||V node layout -------------
__global__ void pack_kv() {
    int m = blockIdx.x;
    int t = threadIdx.x;          // 0..255
    if (t < 128) {
        float2 k = ((const float2*)(g_K32 + (size_t)m * DIM))[t];
        g_KV2[(size_t)m * 256 + t] = __float22half2_rn(k);
    } else {
        float2 v = ((const float2*)(g_V + (size_t)m * DIM))[t - 128];
        g_KV2[(size_t)m * 256 + t] = __float22half2_rn(v);
    }
}

// ---------------- kernel 3: column sums of V (deterministic 2-pass) --------
__global__ void colsum_part() {
    int c = threadIdx.x;
    int b = blockIdx.x;
    float s = 0.0f;
    int r0 = b * (NN / 64);
    for (int r = r0; r < r0 + NN / 64; r++)
        s += g_V[(size_t)r * DIM + c];
    g_partial[b * DIM + c] = s;
}

__global__ void colsum_final() {
    int c = threadIdx.x;
    float s = 0.0f;
    #pragma unroll
    for (int b = 0; b < 64; b++) s += g_partial[b * DIM + c];
    g_colsum[c] = s;
}

// ---------------- fp16 dot / accumulate helpers -----------------------------
__device__ __forceinline__ float dot8h(float4 q0, float4 q1, uint4 k) {
    const __half2* kb = (const __half2*)&k;
    float2 a = __half22float2(kb[0]);
    float2 b = __half22float2(kb[1]);
    float2 c = __half22float2(kb[2]);
    float2 d = __half22float2(kb[3]);
    return q0.x * a.x + q0.y * a.y + q0.z * b.x + q0.w * b.y
         + q1.x * c.x + q1.y * c.y + q1.z * d.x + q1.w * d.y;
}

__device__ __forceinline__ void accum8h(float* acc, uint4 v, float w) {
    const __half2* vb = (const __half2*)&v;
    float2 a = __half22float2(vb[0]);
    float2 b = __half22float2(vb[1]);
    float2 c = __half22float2(vb[2]);
    float2 d = __half22float2(vb[3]);
    acc[0] += w * a.x; acc[1] += w * a.y;
    acc[2] += w * b.x; acc[3] += w * b.y;
    acc[4] += w * c.x; acc[5] += w * c.y;
    acc[6] += w * d.x; acc[7] += w * d.y;
}

// ---------------- cp.async helpers ------------------------------------------
__device__ __forceinline__ void cp16(unsigned int smem_dst, const void* gsrc) {
    asm volatile("cp.async.cg.shared.global [%0], [%1], 16;"
                 :: "r"(smem_dst), "l"(gsrc) : "memory");
}
__device__ __forceinline__ void cp_commit() {
    asm volatile("cp.async.commit_group;" ::: "memory");
}

// ---------------- kernel 4: fused scan + sparse attention -------------------
// out_i = (colsum(V) + sum_edges expm1(s_ij) * v_j) / (N + sum_edges expm1(s_ij))
// TWO warps per row (each owns half the columns). The adj stream is DECOUPLED
// from the gather via cp.async.cg double-buffering: while a warp gathers chunk
// c's edges (fp16 K||V, L2-hot), chunk c+1's 512-col adj slice streams into
// smem (L2-only path, bypassing L1). Each lane owns 16 contiguous cols/chunk.
__global__ __launch_bounds__(128) void fused_attn(const float* __restrict__ adj,
                                                  float* __restrict__ out) {
    __shared__ uint4 s_adj[4][2][32][4];   // [warp][buf][lane][16B-chunk] 16KB
    __shared__ int   s_cols[4][CHUNK_CAP];
    __shared__ float s_acc[2][32][8];
    __shared__ float s_dsum[2];

    int w    = threadIdx.x >> 5;     // 0..3
    int lane = threadIdx.x & 31;
    int rib  = w >> 1;               // row in block: 0,1
    int half = w & 1;                // column half: 0,1
    int row  = blockIdx.x * 2 + rib;

    const float4* qp = (const float4*)(g_Q + (size_t)row * DIM);
    float4 q0 = qp[lane * 2];        // dims lane*8   .. lane*8+3
    float4 q1 = qp[lane * 2 + 1];    // dims lane*8+4 .. lane*8+7

    float acc[8];
    #pragma unroll
    for (int i = 0; i < 8; i++) acc[i] = 0.0f;
    float dsum = 0.0f;

    int* sc = s_cols[w];
    const uint4* kvbase = (const uint4*)g_KV2;
    const float* arow = adj + (size_t)row * NN + half * (NN / 2);

    unsigned int sa_base =
        (unsigned int)__cvta_generic_to_shared(&s_adj[w][0][lane][0]);
    // buf stride in bytes: [2] dim -> 32*4*16 = 2048
    // stage chunk 0
    #pragma unroll
    for (int q = 0; q < 4; q++)
        cp16(sa_base + q * 16, arow + (size_t)lane * 16 + q * 4);
    cp_commit();

    for (int chunk = 0; chunk < NCHUNK; chunk++) {
        // issue prefetch of next chunk into the other buffer
        if (chunk + 1 < NCHUNK) {
            unsigned int dst = sa_base + ((chunk + 1) & 1) * 2048;
            const float* src = arow + (size_t)(chunk + 1) * ACHUNK + lane * 16;
            #pragma unroll
            for (int q = 0; q < 4; q++)
                cp16(dst + q * 16, src + q * 4);
            cp_commit();
            asm volatile("cp.async.wait_group 1;" ::: "memory");
        } else {
            asm volatile("cp.async.wait_group 0;" ::: "memory");
        }

        // --- scan this chunk's 512 cols from smem: 16 cols per lane ---
        const uint4* sb = s_adj[w][chunk & 1][lane];
        uint4 a0 = sb[0], a1 = sb[1], a2 = sb[2], a3 = sb[3];

        unsigned m = 0;
        m |= (a0.x?1u:0u)     | (a0.y?2u:0u)      | (a0.z?4u:0u)      | (a0.w?8u:0u);
        m |= (a1.x?16u:0u)    | (a1.y?32u:0u)     | (a1.z?64u:0u)     | (a1.w?128u:0u);
        m |= (a2.x?256u:0u)   | (a2.y?512u:0u)    | (a2.z?1024u:0u)   | (a2.w?2048u:0u);
        m |= (a3.x?4096u:0u)  | (a3.y?8192u:0u)   | (a3.z?16384u:0u)  | (a3.w?32768u:0u);

        int cnt  = __popc(m);
        int incl = cnt;
        #pragma unroll
        for (int o = 1; o < 32; o <<= 1) {
            int n = __shfl_up_sync(0xFFFFFFFFu, incl, o);
            if (lane >= o) incl += n;
        }
        int pos   = incl - cnt;
        int total = __shfl_sync(0xFFFFFFFFu, incl, 31);

        int myBase = half * (NN / 2) + chunk * ACHUNK + lane * 16;
        unsigned mm = m;
        while (mm) {
            int b = __ffs(mm) - 1;
            mm &= mm - 1;
            if (pos < CHUNK_CAP) sc[pos] = myBase + b;
            pos++;
        }
        if (total > CHUNK_CAP) total = CHUNK_CAP;
        __syncwarp();

        // --- gather: 1KB/edge fp16 K||V, unroll-2 for MLP ---
        int e = 0;
        for (; e + 2 <= total; e += 2) {
            int j0 = sc[e], j1 = sc[e + 1];
            const uint4* kv0 = kvbase + (size_t)j0 * 64;
            const uint4* kv1 = kvbase + (size_t)j1 * 64;
            uint4 k0 = kv0[lane], v0 = kv0[32 + lane];
            uint4 k1 = kv1[lane], v1 = kv1[32 + lane];

            float d0 = dot8h(q0, q1, k0);
            float d1 = dot8h(q0, q1, k1);
            #pragma unroll
            for (int o = 16; o > 0; o >>= 1) {
                d0 += __shfl_xor_sync(0xFFFFFFFFu, d0, o);
                d1 += __shfl_xor_sync(0xFFFFFFFFu, d1, o);
            }
            float w0 = expm1f(d0);
            float w1 = expm1f(d1);
            accum8h(acc, v0, w0);
            accum8h(acc, v1, w1);
            dsum += w0 + w1;
        }
        if (e < total) {
            int j = sc[e];
            const uint4* kv = kvbase + (size_t)j * 64;
            uint4 k = kv[lane], v = kv[32 + lane];
            float d = dot8h(q0, q1, k);
            #pragma unroll
            for (int o = 16; o > 0; o >>= 1)
                d += __shfl_xor_sync(0xFFFFFFFFu, d, o);
            float wv = expm1f(d);
            accum8h(acc, v, wv);
            dsum += wv;
        }
        __syncwarp();   // sc reuse next chunk
    }

    // --- combine the two half-row warps ---
    if (half == 1) {
        #pragma unroll
        for (int i = 0; i < 8; i++) s_acc[rib][lane][i] = acc[i];
        if (lane == 0) s_dsum[rib] = dsum;
    }
    __syncthreads();
    if (half == 0) {
        #pragma unroll
        for (int i = 0; i < 8; i++) acc[i] += s_acc[rib][lane][i];
        dsum += s_dsum[rib];

        float inv = 1.0f / ((float)NN + dsum);
        const float4* cs = (const float4*)g_colsum;
        float4 c0 = cs[lane * 2], c1 = cs[lane * 2 + 1];

        float4* op = (float4*)(out + (size_t)row * DIM + lane * 8);
        op[0] = make_float4((c0.x + acc[0]) * inv, (c0.y + acc[1]) * inv,
                            (c0.z + acc[2]) * inv, (c0.w + acc[3]) * inv);
        op[1] = make_float4((c1.x + acc[4]) * inv, (c1.y + acc[5]) * inv,
                            (c1.z + acc[6]) * inv, (c1.w + acc[7]) * inv);
    }
}

// ---------------- launcher --------------------------------------------------
extern "C" void kernel_launch(void* const* d_in, const int* in_sizes, int n_in,
                              void* d_out, int out_size) {
    const float* adj = (const float*)d_in[0];
    const float* h   = (const float*)d_in[1];
    const float* Wq  = (const float*)d_in[2];
    const float* Wk  = (const float*)d_in[3];
    const float* Wv  = (const float*)d_in[4];
    float* out = (float*)d_out;

    int tot = NH + 3 * NW;
    convert_inputs<<<(tot + 255) / 256, 256>>>(h, Wq, Wk, Wv);
    wmma_gemm<<<dim3(NN / 128, DIM / 128, 3), 256>>>();
    pack_kv<<<NN, 256>>>();
    colsum_part<<<64, 256>>>();
    colsum_final<<<1, 256>>>();
    fused_attn<<<NN / 2, 128>>>(adj, out);
}